// round 8
// baseline (speedup 1.0000x reference)
#include <cuda_runtime.h>
#include <math.h>

// Problem constants
#define LSEQ 8192
#define NFFT 16384          // 2*LSEQ = 32*32*16
#define DM   768
#define EMB  33
#define FO   64
#define SHIFT_C 0.05f
#define NT   512            // FFT threads per CTA

// Pad 1 float2 per 16: PHYS(i) = i + (i>>4).  (verified conflict-free R5)
#define DPAD 17408
#define SMEM_BYTES (DPAD * (int)sizeof(float2))          // 139264 B

// ---------------- scratch (device globals: no allocations allowed) ----------
__device__ float g_k[DM * LSEQ];                         // filter k[d][l]
__device__ __align__(16) float2 g_Kf[(size_t)DM * NFFT]; // (spectrum + D)/N, scrambled

// e^{-2*pi*i*c/32}, c = 0..7
__constant__ float2 cR32[8] = {
    { 1.0f, 0.0f },
    { 0.98078528040323044f, -0.19509032201612827f },
    { 0.92387953251128674f, -0.38268343236508977f },
    { 0.83146961230254524f, -0.55557023301960222f },
    { 0.70710678118654752f, -0.70710678118654752f },
    { 0.55557023301960222f, -0.83146961230254524f },
    { 0.38268343236508977f, -0.92387953251128674f },
    { 0.19509032201612827f, -0.98078528040323044f }
};
// e^{-2*pi*i*c/16}, c = 0..3
__constant__ float2 cR16[4] = {
    { 1.0f, 0.0f },
    { 0.92387953251128674f, -0.38268343236508977f },
    { 0.70710678118654752f, -0.70710678118654752f },
    { 0.38268343236508977f, -0.92387953251128674f }
};
#define R8X 0.70710678118654752f

// ---------------- complex helpers ----------------
__device__ __forceinline__ float2 cadd(float2 a, float2 b){ return make_float2(a.x+b.x, a.y+b.y); }
__device__ __forceinline__ float2 csub(float2 a, float2 b){ return make_float2(a.x-b.x, a.y-b.y); }
__device__ __forceinline__ float2 cmul(float2 a, float2 b){
    return make_float2(a.x*b.x - a.y*b.y, a.x*b.y + a.y*b.x);
}
__device__ __forceinline__ float2 conjf2(float2 a){ return make_float2(a.x, -a.y); }

// radix-4 DIF forward core (no twiddle)
__device__ __forceinline__ void bf4f(float2 x0, float2 x1, float2 x2, float2 x3,
                                     float2& a0, float2& a1, float2& a2, float2& a3) {
    float2 t0 = cadd(x0, x2), t1 = csub(x0, x2);
    float2 t2 = cadd(x1, x3), t3 = csub(x1, x3);
    float2 mi = make_float2(t3.y, -t3.x);                // -i * t3
    a0 = cadd(t0, t2);
    a1 = cadd(t1, mi);
    a2 = csub(t0, t2);
    a3 = csub(t1, mi);
}
// radix-4 inverse core (unscaled)
__device__ __forceinline__ void bf4i(float2 x0, float2 x1, float2 x2, float2 x3,
                                     float2& a0, float2& a1, float2& a2, float2& a3) {
    float2 t0 = cadd(x0, x2), t1 = csub(x0, x2);
    float2 t2 = cadd(x1, x3), t3 = csub(x1, x3);
    float2 pi = make_float2(-t3.y, t3.x);                // +i * t3
    a0 = cadd(t0, t2);
    a1 = cadd(t1, pi);
    a2 = csub(t0, t2);
    a3 = csub(t1, pi);
}

// ---------------- register radix-32 (4*4*2 DIF), external span S = 1<<LS ----
// HALF: x[16..31] implicitly zero on entry.
template<int LS, bool HALF>
__device__ __forceinline__ void fft32_fwd(float2* x, int j) {
    const float C = -6.2831853071795864769f / (float)(1 << (LS + 5));
    float sb, cb;
    __sincosf(C * (float)j, &sb, &cb);
    const float2 b = make_float2(cb, sb);
    // stage A: span 8
    #pragma unroll
    for (int c = 0; c < 8; c++) {
        float2 w1 = cmul(b, cR32[c]);
        float2 w2 = cmul(w1, w1), w3 = cmul(w2, w1);
        float2 a0, a1, a2, a3;
        if (HALF) {
            float2 x0 = x[c], x1 = x[c + 8];
            a0 = cadd(x0, x1);
            a1 = make_float2(x0.x + x1.y, x0.y - x1.x);  // x0 - i*x1
            a2 = csub(x0, x1);
            a3 = make_float2(x0.x - x1.y, x0.y + x1.x);  // x0 + i*x1
        } else {
            bf4f(x[c], x[c+8], x[c+16], x[c+24], a0, a1, a2, a3);
        }
        x[c]      = a0;
        x[c + 8]  = cmul(a1, w1);
        x[c + 16] = cmul(a2, w2);
        x[c + 24] = cmul(a3, w3);
    }
    const float2 b2 = cmul(b, b);
    const float2 b4 = cmul(b2, b2);
    const float2 b4r = cmul(b4, make_float2(R8X, -R8X)); // b4 * e^{-i pi/4}
    // stage B: span 2
    #pragma unroll
    for (int g = 0; g < 4; g++) {
        #pragma unroll
        for (int c2 = 0; c2 < 2; c2++) {
            const int i = 8 * g + c2;
            float2 w1 = (c2 == 0) ? b4 : b4r;
            float2 w2 = cmul(w1, w1), w3 = cmul(w2, w1);
            float2 a0, a1, a2, a3;
            bf4f(x[i], x[i+2], x[i+4], x[i+6], a0, a1, a2, a3);
            x[i]     = a0;
            x[i + 2] = cmul(a1, w1);
            x[i + 4] = cmul(a2, w2);
            x[i + 6] = cmul(a3, w3);
        }
    }
    const float2 b8  = cmul(b4, b4);
    const float2 b16 = cmul(b8, b8);
    // stage C: radix-2, span 1
    #pragma unroll
    for (int m = 0; m < 16; m++) {
        float2 x0 = x[2*m], x1 = x[2*m + 1];
        x[2*m]     = cadd(x0, x1);
        x[2*m + 1] = cmul(csub(x0, x1), b16);
    }
}

// Inverse (unscaled, gain 32).  HALFOUT: only outputs r<16 are produced.
template<int LS, bool HALFOUT>
__device__ __forceinline__ void fft32_inv(float2* x, int j) {
    const float C = -6.2831853071795864769f / (float)(1 << (LS + 5));
    float sb, cb;
    __sincosf(C * (float)j, &sb, &cb);
    const float2 b   = make_float2(cb, -sb);             // conj
    const float2 b2  = cmul(b, b);
    const float2 b4  = cmul(b2, b2);
    const float2 b8  = cmul(b4, b4);
    const float2 b16 = cmul(b8, b8);
    // stage C'
    #pragma unroll
    for (int m = 0; m < 16; m++) {
        float2 z1 = cmul(x[2*m + 1], b16);
        float2 x0 = x[2*m];
        x[2*m]     = cadd(x0, z1);
        x[2*m + 1] = csub(x0, z1);
    }
    // stage B'
    const float2 b4r = cmul(b4, make_float2(R8X, R8X));  // b4 * e^{+i pi/4}
    #pragma unroll
    for (int g = 0; g < 4; g++) {
        #pragma unroll
        for (int c2 = 0; c2 < 2; c2++) {
            const int i = 8 * g + c2;
            float2 w1 = (c2 == 0) ? b4 : b4r;
            float2 w2 = cmul(w1, w1), w3 = cmul(w2, w1);
            float2 z0 = x[i];
            float2 z1 = cmul(x[i + 2], w1);
            float2 z2 = cmul(x[i + 4], w2);
            float2 z3 = cmul(x[i + 6], w3);
            bf4i(z0, z1, z2, z3, x[i], x[i+2], x[i+4], x[i+6]);
        }
    }
    // stage A'
    #pragma unroll
    for (int c = 0; c < 8; c++) {
        float2 w1 = cmul(b, conjf2(cR32[c]));
        float2 w2 = cmul(w1, w1), w3 = cmul(w2, w1);
        float2 z0 = x[c];
        float2 z1 = cmul(x[c + 8],  w1);
        float2 z2 = cmul(x[c + 16], w2);
        float2 z3 = cmul(x[c + 24], w3);
        if (HALFOUT) {
            float2 t0 = cadd(z0, z2), t1 = csub(z0, z2);
            float2 t2 = cadd(z1, z3), t3 = csub(z1, z3);
            float2 pi = make_float2(-t3.y, t3.x);
            x[c]     = cadd(t0, t2);
            x[c + 8] = cadd(t1, pi);
        } else {
            bf4i(z0, z1, z2, z3, x[c], x[c+8], x[c+16], x[c+24]);
        }
    }
}

// ---------------- 16-point cores, all-constant twiddles ---------------------
__device__ __forceinline__ void fft16c_fwd(float2* x) {
    #pragma unroll
    for (int c = 0; c < 4; c++) {
        float2 w1 = cR16[c];
        float2 w2 = cmul(w1, w1), w3 = cmul(w2, w1);
        float2 a0, a1, a2, a3;
        bf4f(x[c], x[c+4], x[c+8], x[c+12], a0, a1, a2, a3);
        x[c]      = a0;
        x[c + 4]  = cmul(a1, w1);
        x[c + 8]  = cmul(a2, w2);
        x[c + 12] = cmul(a3, w3);
    }
    #pragma unroll
    for (int m = 0; m < 4; m++) {
        float2 a0, a1, a2, a3;
        bf4f(x[4*m], x[4*m+1], x[4*m+2], x[4*m+3], a0, a1, a2, a3);
        x[4*m] = a0; x[4*m+1] = a1; x[4*m+2] = a2; x[4*m+3] = a3;
    }
}
__device__ __forceinline__ void fft16c_inv(float2* x) {
    #pragma unroll
    for (int m = 0; m < 4; m++) {
        float2 a0, a1, a2, a3;
        bf4i(x[4*m], x[4*m+1], x[4*m+2], x[4*m+3], a0, a1, a2, a3);
        x[4*m] = a0; x[4*m+1] = a1; x[4*m+2] = a2; x[4*m+3] = a3;
    }
    #pragma unroll
    for (int c = 0; c < 4; c++) {
        float2 w1 = conjf2(cR16[c]);
        float2 w2 = cmul(w1, w1), w3 = cmul(w2, w1);
        float2 z1 = cmul(x[c + 4],  w1);
        float2 z2 = cmul(x[c + 8],  w2);
        float2 z3 = cmul(x[c + 12], w3);
        bf4i(x[c], z1, z2, z3, x[c], x[c+4], x[c+8], x[c+12]);
    }
}

// ---------------- fused MLP + projection + modulation -> k[d][l] ------------
// Block: 256 threads, tile 32 l x 128 d.  MLP recomputed per tile (cheap);
// W1/W2/W3 + Wout tile + S cached in dynamic smem.
#define FW1 0                      // 33*64 = 2112 floats
#define FW2 2112                   // 64*64 = 4096
#define FW3 6208                   // 64*64 = 4096
#define FSS 10304                  // 32*64 = 2048
#define FWS 12352                  // 64*128 = 8192
#define FILT_SMEM_FLOATS 20544
#define FILT_SMEM_BYTES (FILT_SMEM_FLOATS * 4)   // 82176 B

__global__ void __launch_bounds__(256)
filt_kernel(const float* __restrict__ z, const float* __restrict__ freq,
            const float* __restrict__ W1, const float* __restrict__ b1,
            const float* __restrict__ W2, const float* __restrict__ b2,
            const float* __restrict__ W3, const float* __restrict__ b3,
            const float* __restrict__ Wout, const float* __restrict__ t,
            const float* __restrict__ deltas) {
    extern __shared__ float fsm[];
    __shared__ float zs[4][EMB];
    __shared__ float as[4][FO];
    __shared__ float bs[4][FO];

    const int tid = threadIdx.x;
    const int l0  = blockIdx.x * 32;
    const int d0  = blockIdx.y * 128;

    // load weights once per block
    for (int i = tid; i < EMB * FO; i += 256) fsm[FW1 + i] = W1[i];
    for (int i = tid; i < FO * FO; i += 256)  fsm[FW2 + i] = W2[i];
    for (int i = tid; i < FO * FO; i += 256)  fsm[FW3 + i] = W3[i];
    for (int i = tid; i < FO * 128; i += 256)
        fsm[FWS + i] = Wout[(i >> 7) * DM + d0 + (i & 127)];
    __syncthreads();

    // MLP: 4 l's per chunk, 8 chunks -> S[32][64]
    const int lg = tid >> 6;
    const int f  = tid & 63;
    const float fr  = freq[f];
    const float b1f = b1[f], b2f = b2[f], b3f = b3[f];

    for (int c = 0; c < 8; c++) {
        const int l = l0 + c * 4 + lg;
        if (f < EMB) zs[lg][f] = z[l * EMB + f];
        __syncthreads();
        float acc = b1f;
        #pragma unroll
        for (int e = 0; e < EMB; e++) acc += zs[lg][e] * fsm[FW1 + e * FO + f];
        as[lg][f] = sinf(fr * acc);
        __syncthreads();
        acc = b2f;
        #pragma unroll
        for (int e = 0; e < FO; e++) acc += as[lg][e] * fsm[FW2 + e * FO + f];
        bs[lg][f] = sinf(fr * acc);
        __syncthreads();
        acc = b3f;
        #pragma unroll
        for (int e = 0; e < FO; e++) acc += bs[lg][e] * fsm[FW3 + e * FO + f];
        fsm[FSS + (c * 4 + lg) * FO + f] = sinf(fr * acc);
        __syncthreads();
    }

    // projection GEMM + exponential modulation
    const int dl  = tid & 127;
    const int lgp = tid >> 7;
    float acc[16];
    #pragma unroll
    for (int i = 0; i < 16; i++) acc[i] = 0.0f;
    #pragma unroll
    for (int ff = 0; ff < FO; ff++) {
        const float w = fsm[FWS + ff * 128 + dl];
        #pragma unroll
        for (int i = 0; i < 16; i++)
            acc[i] += fsm[FSS + (lgp * 16 + i) * FO + ff] * w;
    }
    const int d = d0 + dl;
    const float ad = fabsf(deltas[d]);
    #pragma unroll
    for (int i = 0; i < 16; i++) {
        const int l = l0 + lgp * 16 + i;
        g_k[(size_t)d * LSEQ + l] = acc[i] * (expf(-t[l] * ad) + SHIFT_C);
    }
}

// ---------------- kernel spectrum (+D baked in) -----------------------------
__global__ void __launch_bounds__(NT, 1)
kf_kernel(const float* __restrict__ Dbias) {
    extern __shared__ float2 d[];
    const int tid = threadIdx.x;
    const int ch  = blockIdx.x;

    const float* krow = g_k + (size_t)ch * LSEQ;
    const int jb = tid + (tid >> 4);                     // PHYS(tid)

    // P1: radix-32, S=512; top half zero
    {
        float2 xv[32];
        #pragma unroll
        for (int r = 0; r < 16; r++)
            xv[r] = make_float2(krow[tid + (r << 9)], 0.0f);
        fft32_fwd<9, true>(xv, tid);
        #pragma unroll
        for (int r = 0; r < 32; r++) d[jb + 544 * r] = xv[r];
    }
    __syncthreads();

    const int j2 = tid & 15;
    const int b0 = (tid >> 4) * 544 + j2;

    // P2: radix-32, S=16
    {
        float2 xv[32];
        #pragma unroll
        for (int r = 0; r < 32; r++) xv[r] = d[b0 + 17 * r];
        fft32_fwd<4, false>(xv, j2);
        #pragma unroll
        for (int r = 0; r < 32; r++) d[b0 + 17 * r] = xv[r];
    }
    __syncthreads();

    // P3: const-twiddle fwd16 + bake (spec + D)/N, store to g_Kf
    float2* outp = g_Kf + (size_t)ch * NFFT;
    const float sc = 1.0f / (float)NFFT;
    const float Dd = Dbias[ch];
    #pragma unroll
    for (int k = 0; k < 2; k++) {
        const int q  = tid + k * NT;
        const int pb = 17 * q;                           // PHYS(16q)
        float2 xv[16];
        #pragma unroll
        for (int r = 0; r < 16; r++) xv[r] = d[pb + r];
        fft16c_fwd(xv);
        float4* o4 = reinterpret_cast<float4*>(outp + 16 * q);
        #pragma unroll
        for (int i = 0; i < 8; i++) {
            o4[i] = make_float4((xv[2*i].x + Dd) * sc, xv[2*i].y * sc,
                                (xv[2*i+1].x + Dd) * sc, xv[2*i+1].y * sc);
        }
    }
}

// ---------------- conv ------------------------------------------------------
// grid = dim3(2, DM): the two batch-pair CTAs of a channel are adjacent in
// linear block order -> co-resident -> second Kf read hits L2.
__global__ void __launch_bounds__(NT, 1)
conv_kernel(const float* __restrict__ x, float* __restrict__ out) {
    extern __shared__ float2 d[];
    const int tid = threadIdx.x;
    const int ch  = blockIdx.y;
    const int p   = blockIdx.x;                          // batch pair

    const float* u0 = x + ((size_t)(2*p)     * DM + ch) * LSEQ;
    const float* u1 = x + ((size_t)(2*p + 1) * DM + ch) * LSEQ;
    const float2* kf = g_Kf + (size_t)ch * NFFT;

    // prefetch this thread's Kf lines into L2 (consumed in P3, ~2500 cyc away)
    asm volatile("prefetch.global.L2 [%0];" :: "l"(kf + 16 * tid));
    asm volatile("prefetch.global.L2 [%0];" :: "l"(kf + 16 * (tid + NT)));

    const int jb = tid + (tid >> 4);

    // P1 fwd: radix-32, S=512; pack u0 + i*u1; top half zero
    {
        float2 xv[32];
        #pragma unroll
        for (int r = 0; r < 16; r++) {
            const int i = tid + (r << 9);
            xv[r] = make_float2(u0[i], u1[i]);
        }
        fft32_fwd<9, true>(xv, tid);
        #pragma unroll
        for (int r = 0; r < 32; r++) d[jb + 544 * r] = xv[r];
    }
    __syncthreads();

    const int j2 = tid & 15;
    const int b0 = (tid >> 4) * 544 + j2;

    // P2 fwd: radix-32, S=16
    {
        float2 xv[32];
        #pragma unroll
        for (int r = 0; r < 32; r++) xv[r] = d[b0 + 17 * r];
        fft32_fwd<4, false>(xv, j2);
        #pragma unroll
        for (int r = 0; r < 32; r++) d[b0 + 17 * r] = xv[r];
    }
    __syncthreads();

    // P3: const-twiddle fwd16 -> * Kf (D baked in) -> const-twiddle inv16
    #pragma unroll
    for (int k = 0; k < 2; k++) {
        const int q  = tid + k * NT;
        const int pb = 17 * q;
        float4 kreg[8];
        const float4* kf4 = reinterpret_cast<const float4*>(kf + 16 * q);
        #pragma unroll
        for (int i = 0; i < 8; i++) kreg[i] = kf4[i];    // prefetch over fwd16
        float2 xv[16];
        #pragma unroll
        for (int r = 0; r < 16; r++) xv[r] = d[pb + r];
        fft16c_fwd(xv);
        #pragma unroll
        for (int i = 0; i < 8; i++) {
            xv[2*i]   = cmul(xv[2*i],   make_float2(kreg[i].x, kreg[i].y));
            xv[2*i+1] = cmul(xv[2*i+1], make_float2(kreg[i].z, kreg[i].w));
        }
        fft16c_inv(xv);
        #pragma unroll
        for (int r = 0; r < 16; r++) d[pb + r] = xv[r];
    }
    __syncthreads();

    // P2' inv
    {
        float2 xv[32];
        #pragma unroll
        for (int r = 0; r < 32; r++) xv[r] = d[b0 + 17 * r];
        fft32_inv<4, false>(xv, j2);
        #pragma unroll
        for (int r = 0; r < 32; r++) d[b0 + 17 * r] = xv[r];
    }
    __syncthreads();

    // P1' inv: half output, direct global store
    float* o0 = out + ((size_t)(2*p)     * DM + ch) * LSEQ;
    float* o1 = out + ((size_t)(2*p + 1) * DM + ch) * LSEQ;
    {
        float2 xv[32];
        #pragma unroll
        for (int r = 0; r < 32; r++) xv[r] = d[jb + 544 * r];
        fft32_inv<9, true>(xv, tid);
        #pragma unroll
        for (int r = 0; r < 16; r++) {
            const int i = tid + (r << 9);
            o0[i] = xv[r].x;
            o1[i] = xv[r].y;
        }
    }
}

// ---------------- launch ----------------------------------------------------
// Input order (metadata): x, z, t, freq, W1, b1, W2, b2, W3, b3, Wout, deltas, D
extern "C" void kernel_launch(void* const* d_in, const int* in_sizes, int n_in,
                              void* d_out, int out_size) {
    (void)in_sizes; (void)n_in; (void)out_size;
    const float* x      = (const float*)d_in[0];
    const float* z      = (const float*)d_in[1];
    const float* t      = (const float*)d_in[2];
    const float* freq   = (const float*)d_in[3];
    const float* W1     = (const float*)d_in[4];
    const float* b1     = (const float*)d_in[5];
    const float* W2     = (const float*)d_in[6];
    const float* b2     = (const float*)d_in[7];
    const float* W3     = (const float*)d_in[8];
    const float* b3     = (const float*)d_in[9];
    const float* Wout   = (const float*)d_in[10];
    const float* deltas = (const float*)d_in[11];
    const float* Dbias  = (const float*)d_in[12];
    float* out = (float*)d_out;

    cudaFuncSetAttribute(filt_kernel, cudaFuncAttributeMaxDynamicSharedMemorySize, FILT_SMEM_BYTES);
    cudaFuncSetAttribute(kf_kernel,   cudaFuncAttributeMaxDynamicSharedMemorySize, SMEM_BYTES);
    cudaFuncSetAttribute(conv_kernel, cudaFuncAttributeMaxDynamicSharedMemorySize, SMEM_BYTES);

    filt_kernel<<<dim3(LSEQ / 32, DM / 128), 256, FILT_SMEM_BYTES>>>(
        z, freq, W1, b1, W2, b2, W3, b3, Wout, t, deltas);
    kf_kernel<<<DM, NT, SMEM_BYTES>>>(Dbias);
    conv_kernel<<<dim3(2, DM), NT, SMEM_BYTES>>>(x, out);
}

// round 9
// speedup vs baseline: 1.3510x; 1.3510x over previous
#include <cuda_runtime.h>
#include <math.h>

// Problem constants
#define LSEQ 8192
#define NFFT 16384          // 2*LSEQ = 32*32*16
#define DM   768
#define EMB  33
#define FO   64
#define SHIFT_C 0.05f
#define NT   512            // FFT threads per CTA

// Pad 1 float2 per 16: PHYS(i) = i + (i>>4).  (verified conflict-free R5)
#define DPAD 17408
#define SMEM_BYTES (DPAD * (int)sizeof(float2))          // 139264 B

// ---------------- scratch (device globals: no allocations allowed) ----------
__device__ float g_S[LSEQ * FO];                         // post-MLP activations
__device__ float g_k[DM * LSEQ];                         // filter k[d][l]
__device__ __align__(16) float2 g_Kf[(size_t)DM * NFFT]; // (spectrum + D)/N, scrambled

// e^{-2*pi*i*c/32}, c = 0..7
__constant__ float2 cR32[8] = {
    { 1.0f, 0.0f },
    { 0.98078528040323044f, -0.19509032201612827f },
    { 0.92387953251128674f, -0.38268343236508977f },
    { 0.83146961230254524f, -0.55557023301960222f },
    { 0.70710678118654752f, -0.70710678118654752f },
    { 0.55557023301960222f, -0.83146961230254524f },
    { 0.38268343236508977f, -0.92387953251128674f },
    { 0.19509032201612827f, -0.98078528040323044f }
};
// e^{-2*pi*i*c/16}, c = 0..3
__constant__ float2 cR16[4] = {
    { 1.0f, 0.0f },
    { 0.92387953251128674f, -0.38268343236508977f },
    { 0.70710678118654752f, -0.70710678118654752f },
    { 0.38268343236508977f, -0.92387953251128674f }
};
#define R8X 0.70710678118654752f

// ---------------- complex helpers ----------------
__device__ __forceinline__ float2 cadd(float2 a, float2 b){ return make_float2(a.x+b.x, a.y+b.y); }
__device__ __forceinline__ float2 csub(float2 a, float2 b){ return make_float2(a.x-b.x, a.y-b.y); }
__device__ __forceinline__ float2 cmul(float2 a, float2 b){
    return make_float2(a.x*b.x - a.y*b.y, a.x*b.y + a.y*b.x);
}
__device__ __forceinline__ float2 conjf2(float2 a){ return make_float2(a.x, -a.y); }

// radix-4 DIF forward core (no twiddle)
__device__ __forceinline__ void bf4f(float2 x0, float2 x1, float2 x2, float2 x3,
                                     float2& a0, float2& a1, float2& a2, float2& a3) {
    float2 t0 = cadd(x0, x2), t1 = csub(x0, x2);
    float2 t2 = cadd(x1, x3), t3 = csub(x1, x3);
    float2 mi = make_float2(t3.y, -t3.x);                // -i * t3
    a0 = cadd(t0, t2);
    a1 = cadd(t1, mi);
    a2 = csub(t0, t2);
    a3 = csub(t1, mi);
}
// radix-4 inverse core (unscaled)
__device__ __forceinline__ void bf4i(float2 x0, float2 x1, float2 x2, float2 x3,
                                     float2& a0, float2& a1, float2& a2, float2& a3) {
    float2 t0 = cadd(x0, x2), t1 = csub(x0, x2);
    float2 t2 = cadd(x1, x3), t3 = csub(x1, x3);
    float2 pi = make_float2(-t3.y, t3.x);                // +i * t3
    a0 = cadd(t0, t2);
    a1 = cadd(t1, pi);
    a2 = csub(t0, t2);
    a3 = csub(t1, pi);
}

// ---------------- register radix-32 (4*4*2 DIF), external span S = 1<<LS ----
// HALF: x[16..31] implicitly zero on entry.
template<int LS, bool HALF>
__device__ __forceinline__ void fft32_fwd(float2* x, int j) {
    const float C = -6.2831853071795864769f / (float)(1 << (LS + 5));
    float sb, cb;
    __sincosf(C * (float)j, &sb, &cb);
    const float2 b = make_float2(cb, sb);
    // stage A: span 8
    #pragma unroll
    for (int c = 0; c < 8; c++) {
        float2 w1 = cmul(b, cR32[c]);
        float2 w2 = cmul(w1, w1), w3 = cmul(w2, w1);
        float2 a0, a1, a2, a3;
        if (HALF) {
            float2 x0 = x[c], x1 = x[c + 8];
            a0 = cadd(x0, x1);
            a1 = make_float2(x0.x + x1.y, x0.y - x1.x);  // x0 - i*x1
            a2 = csub(x0, x1);
            a3 = make_float2(x0.x - x1.y, x0.y + x1.x);  // x0 + i*x1
        } else {
            bf4f(x[c], x[c+8], x[c+16], x[c+24], a0, a1, a2, a3);
        }
        x[c]      = a0;
        x[c + 8]  = cmul(a1, w1);
        x[c + 16] = cmul(a2, w2);
        x[c + 24] = cmul(a3, w3);
    }
    const float2 b2 = cmul(b, b);
    const float2 b4 = cmul(b2, b2);
    const float2 b4r = cmul(b4, make_float2(R8X, -R8X)); // b4 * e^{-i pi/4}
    // stage B: span 2
    #pragma unroll
    for (int g = 0; g < 4; g++) {
        #pragma unroll
        for (int c2 = 0; c2 < 2; c2++) {
            const int i = 8 * g + c2;
            float2 w1 = (c2 == 0) ? b4 : b4r;
            float2 w2 = cmul(w1, w1), w3 = cmul(w2, w1);
            float2 a0, a1, a2, a3;
            bf4f(x[i], x[i+2], x[i+4], x[i+6], a0, a1, a2, a3);
            x[i]     = a0;
            x[i + 2] = cmul(a1, w1);
            x[i + 4] = cmul(a2, w2);
            x[i + 6] = cmul(a3, w3);
        }
    }
    const float2 b8  = cmul(b4, b4);
    const float2 b16 = cmul(b8, b8);
    // stage C: radix-2, span 1
    #pragma unroll
    for (int m = 0; m < 16; m++) {
        float2 x0 = x[2*m], x1 = x[2*m + 1];
        x[2*m]     = cadd(x0, x1);
        x[2*m + 1] = cmul(csub(x0, x1), b16);
    }
}

// Inverse (unscaled, gain 32).  HALFOUT: only outputs r<16 are produced.
template<int LS, bool HALFOUT>
__device__ __forceinline__ void fft32_inv(float2* x, int j) {
    const float C = -6.2831853071795864769f / (float)(1 << (LS + 5));
    float sb, cb;
    __sincosf(C * (float)j, &sb, &cb);
    const float2 b   = make_float2(cb, -sb);             // conj
    const float2 b2  = cmul(b, b);
    const float2 b4  = cmul(b2, b2);
    const float2 b8  = cmul(b4, b4);
    const float2 b16 = cmul(b8, b8);
    // stage C'
    #pragma unroll
    for (int m = 0; m < 16; m++) {
        float2 z1 = cmul(x[2*m + 1], b16);
        float2 x0 = x[2*m];
        x[2*m]     = cadd(x0, z1);
        x[2*m + 1] = csub(x0, z1);
    }
    // stage B'
    const float2 b4r = cmul(b4, make_float2(R8X, R8X));  // b4 * e^{+i pi/4}
    #pragma unroll
    for (int g = 0; g < 4; g++) {
        #pragma unroll
        for (int c2 = 0; c2 < 2; c2++) {
            const int i = 8 * g + c2;
            float2 w1 = (c2 == 0) ? b4 : b4r;
            float2 w2 = cmul(w1, w1), w3 = cmul(w2, w1);
            float2 z0 = x[i];
            float2 z1 = cmul(x[i + 2], w1);
            float2 z2 = cmul(x[i + 4], w2);
            float2 z3 = cmul(x[i + 6], w3);
            bf4i(z0, z1, z2, z3, x[i], x[i+2], x[i+4], x[i+6]);
        }
    }
    // stage A'
    #pragma unroll
    for (int c = 0; c < 8; c++) {
        float2 w1 = cmul(b, conjf2(cR32[c]));
        float2 w2 = cmul(w1, w1), w3 = cmul(w2, w1);
        float2 z0 = x[c];
        float2 z1 = cmul(x[c + 8],  w1);
        float2 z2 = cmul(x[c + 16], w2);
        float2 z3 = cmul(x[c + 24], w3);
        if (HALFOUT) {
            float2 t0 = cadd(z0, z2), t1 = csub(z0, z2);
            float2 t2 = cadd(z1, z3), t3 = csub(z1, z3);
            float2 pi = make_float2(-t3.y, t3.x);
            x[c]     = cadd(t0, t2);
            x[c + 8] = cadd(t1, pi);
        } else {
            bf4i(z0, z1, z2, z3, x[c], x[c+8], x[c+16], x[c+24]);
        }
    }
}

// ---------------- 16-point cores, all-constant twiddles ---------------------
__device__ __forceinline__ void fft16c_fwd(float2* x) {
    #pragma unroll
    for (int c = 0; c < 4; c++) {
        float2 w1 = cR16[c];
        float2 w2 = cmul(w1, w1), w3 = cmul(w2, w1);
        float2 a0, a1, a2, a3;
        bf4f(x[c], x[c+4], x[c+8], x[c+12], a0, a1, a2, a3);
        x[c]      = a0;
        x[c + 4]  = cmul(a1, w1);
        x[c + 8]  = cmul(a2, w2);
        x[c + 12] = cmul(a3, w3);
    }
    #pragma unroll
    for (int m = 0; m < 4; m++) {
        float2 a0, a1, a2, a3;
        bf4f(x[4*m], x[4*m+1], x[4*m+2], x[4*m+3], a0, a1, a2, a3);
        x[4*m] = a0; x[4*m+1] = a1; x[4*m+2] = a2; x[4*m+3] = a3;
    }
}
__device__ __forceinline__ void fft16c_inv(float2* x) {
    #pragma unroll
    for (int m = 0; m < 4; m++) {
        float2 a0, a1, a2, a3;
        bf4i(x[4*m], x[4*m+1], x[4*m+2], x[4*m+3], a0, a1, a2, a3);
        x[4*m] = a0; x[4*m+1] = a1; x[4*m+2] = a2; x[4*m+3] = a3;
    }
    #pragma unroll
    for (int c = 0; c < 4; c++) {
        float2 w1 = conjf2(cR16[c]);
        float2 w2 = cmul(w1, w1), w3 = cmul(w2, w1);
        float2 z1 = cmul(x[c + 4],  w1);
        float2 z2 = cmul(x[c + 8],  w2);
        float2 z3 = cmul(x[c + 12], w3);
        bf4i(x[c], z1, z2, z3, x[c], x[c+4], x[c+8], x[c+12]);
    }
}

// ---------------- filter MLP stages 1-3 (R5 version) -------------------------
__global__ void mlp_kernel(const float* __restrict__ z, const float* __restrict__ freq,
                           const float* __restrict__ W1, const float* __restrict__ b1,
                           const float* __restrict__ W2, const float* __restrict__ b2,
                           const float* __restrict__ W3, const float* __restrict__ b3) {
    __shared__ float zs[4][EMB];
    __shared__ float as[4][FO];
    __shared__ float bs[4][FO];
    const int tid = threadIdx.x;
    const int lg  = tid >> 6;
    const int f   = tid & 63;
    const int l   = blockIdx.x * 4 + lg;

    if (f < EMB) zs[lg][f] = z[l * EMB + f];
    __syncthreads();

    const float fr = freq[f];

    float acc = b1[f];
    #pragma unroll
    for (int e = 0; e < EMB; e++) acc += zs[lg][e] * W1[e * FO + f];
    as[lg][f] = sinf(fr * acc);
    __syncthreads();

    acc = b2[f];
    #pragma unroll
    for (int e = 0; e < FO; e++) acc += as[lg][e] * W2[e * FO + f];
    bs[lg][f] = sinf(fr * acc);
    __syncthreads();

    acc = b3[f];
    #pragma unroll
    for (int e = 0; e < FO; e++) acc += bs[lg][e] * W3[e * FO + f];
    g_S[l * FO + f] = sinf(fr * acc);
}

// ---------------- output projection + exponential modulation (R5 version) ---
__global__ void filt_kernel(const float* __restrict__ Wout, const float* __restrict__ t,
                            const float* __restrict__ deltas) {
    __shared__ float Ss[32][FO];
    __shared__ float Ws[FO][128];
    const int tid = threadIdx.x;
    const int l0  = blockIdx.x * 32;
    const int d0  = blockIdx.y * 128;

    for (int i = tid; i < 32 * FO; i += 256)
        Ss[i >> 6][i & 63] = g_S[(l0 + (i >> 6)) * FO + (i & 63)];
    for (int i = tid; i < FO * 128; i += 256)
        Ws[i >> 7][i & 127] = Wout[(i >> 7) * DM + d0 + (i & 127)];
    __syncthreads();

    const int dl  = tid & 127;
    const int lgp = tid >> 7;
    float acc[16];
    #pragma unroll
    for (int i = 0; i < 16; i++) acc[i] = 0.0f;
    #pragma unroll
    for (int f = 0; f < FO; f++) {
        const float w = Ws[f][dl];
        #pragma unroll
        for (int i = 0; i < 16; i++) acc[i] += Ss[lgp * 16 + i][f] * w;
    }
    const int d = d0 + dl;
    const float ad = fabsf(deltas[d]);
    #pragma unroll
    for (int i = 0; i < 16; i++) {
        const int l = l0 + lgp * 16 + i;
        g_k[(size_t)d * LSEQ + l] = acc[i] * (expf(-t[l] * ad) + SHIFT_C);
    }
}

// ---------------- kernel spectrum (+D baked in) -----------------------------
__global__ void __launch_bounds__(NT, 1)
kf_kernel(const float* __restrict__ Dbias) {
    extern __shared__ float2 d[];
    const int tid = threadIdx.x;
    const int ch  = blockIdx.x;

    const float* krow = g_k + (size_t)ch * LSEQ;
    const int jb = tid + (tid >> 4);                     // PHYS(tid)

    // P1: radix-32, S=512; top half zero
    {
        float2 xv[32];
        #pragma unroll
        for (int r = 0; r < 16; r++)
            xv[r] = make_float2(krow[tid + (r << 9)], 0.0f);
        fft32_fwd<9, true>(xv, tid);
        #pragma unroll
        for (int r = 0; r < 32; r++) d[jb + 544 * r] = xv[r];
    }
    __syncthreads();

    const int j2 = tid & 15;
    const int b0 = (tid >> 4) * 544 + j2;

    // P2: radix-32, S=16
    {
        float2 xv[32];
        #pragma unroll
        for (int r = 0; r < 32; r++) xv[r] = d[b0 + 17 * r];
        fft32_fwd<4, false>(xv, j2);
        #pragma unroll
        for (int r = 0; r < 32; r++) d[b0 + 17 * r] = xv[r];
    }
    __syncthreads();

    // P3: const-twiddle fwd16 + bake (spec + D)/N, store to g_Kf
    float2* outp = g_Kf + (size_t)ch * NFFT;
    const float sc = 1.0f / (float)NFFT;
    const float Dd = Dbias[ch];
    #pragma unroll
    for (int k = 0; k < 2; k++) {
        const int q  = tid + k * NT;
        const int pb = 17 * q;                           // PHYS(16q)
        float2 xv[16];
        #pragma unroll
        for (int r = 0; r < 16; r++) xv[r] = d[pb + r];
        fft16c_fwd(xv);
        float4* o4 = reinterpret_cast<float4*>(outp + 16 * q);
        #pragma unroll
        for (int i = 0; i < 8; i++) {
            o4[i] = make_float4((xv[2*i].x + Dd) * sc, xv[2*i].y * sc,
                                (xv[2*i+1].x + Dd) * sc, xv[2*i+1].y * sc);
        }
    }
}

// ---------------- conv ------------------------------------------------------
// grid = dim3(2, DM): the two batch-pair CTAs of a channel are adjacent in
// linear block order -> co-resident -> second Kf read hits L2.
__global__ void __launch_bounds__(NT, 1)
conv_kernel(const float* __restrict__ x, float* __restrict__ out) {
    extern __shared__ float2 d[];
    const int tid = threadIdx.x;
    const int ch  = blockIdx.y;
    const int p   = blockIdx.x;                          // batch pair

    const float* u0 = x + ((size_t)(2*p)     * DM + ch) * LSEQ;
    const float* u1 = x + ((size_t)(2*p + 1) * DM + ch) * LSEQ;
    const float2* kf = g_Kf + (size_t)ch * NFFT;

    // prefetch this thread's Kf lines into L2 (consumed in P3, ~2500 cyc away)
    asm volatile("prefetch.global.L2 [%0];" :: "l"(kf + 16 * tid));
    asm volatile("prefetch.global.L2 [%0];" :: "l"(kf + 16 * (tid + NT)));

    const int jb = tid + (tid >> 4);

    // P1 fwd: radix-32, S=512; pack u0 + i*u1; top half zero
    {
        float2 xv[32];
        #pragma unroll
        for (int r = 0; r < 16; r++) {
            const int i = tid + (r << 9);
            xv[r] = make_float2(u0[i], u1[i]);
        }
        fft32_fwd<9, true>(xv, tid);
        #pragma unroll
        for (int r = 0; r < 32; r++) d[jb + 544 * r] = xv[r];
    }
    __syncthreads();

    const int j2 = tid & 15;
    const int b0 = (tid >> 4) * 544 + j2;

    // P2 fwd: radix-32, S=16
    {
        float2 xv[32];
        #pragma unroll
        for (int r = 0; r < 32; r++) xv[r] = d[b0 + 17 * r];
        fft32_fwd<4, false>(xv, j2);
        #pragma unroll
        for (int r = 0; r < 32; r++) d[b0 + 17 * r] = xv[r];
    }
    __syncthreads();

    // P3: const-twiddle fwd16 -> * Kf (D baked in) -> const-twiddle inv16
    #pragma unroll
    for (int k = 0; k < 2; k++) {
        const int q  = tid + k * NT;
        const int pb = 17 * q;
        float4 kreg[8];
        const float4* kf4 = reinterpret_cast<const float4*>(kf + 16 * q);
        #pragma unroll
        for (int i = 0; i < 8; i++) kreg[i] = kf4[i];    // prefetch over fwd16
        float2 xv[16];
        #pragma unroll
        for (int r = 0; r < 16; r++) xv[r] = d[pb + r];
        fft16c_fwd(xv);
        #pragma unroll
        for (int i = 0; i < 8; i++) {
            xv[2*i]   = cmul(xv[2*i],   make_float2(kreg[i].x, kreg[i].y));
            xv[2*i+1] = cmul(xv[2*i+1], make_float2(kreg[i].z, kreg[i].w));
        }
        fft16c_inv(xv);
        #pragma unroll
        for (int r = 0; r < 16; r++) d[pb + r] = xv[r];
    }
    __syncthreads();

    // P2' inv
    {
        float2 xv[32];
        #pragma unroll
        for (int r = 0; r < 32; r++) xv[r] = d[b0 + 17 * r];
        fft32_inv<4, false>(xv, j2);
        #pragma unroll
        for (int r = 0; r < 32; r++) d[b0 + 17 * r] = xv[r];
    }
    __syncthreads();

    // P1' inv: half output, direct global store
    float* o0 = out + ((size_t)(2*p)     * DM + ch) * LSEQ;
    float* o1 = out + ((size_t)(2*p + 1) * DM + ch) * LSEQ;
    {
        float2 xv[32];
        #pragma unroll
        for (int r = 0; r < 32; r++) xv[r] = d[jb + 544 * r];
        fft32_inv<9, true>(xv, tid);
        #pragma unroll
        for (int r = 0; r < 16; r++) {
            const int i = tid + (r << 9);
            o0[i] = xv[r].x;
            o1[i] = xv[r].y;
        }
    }
}

// ---------------- launch ----------------------------------------------------
// Input order (metadata): x, z, t, freq, W1, b1, W2, b2, W3, b3, Wout, deltas, D
extern "C" void kernel_launch(void* const* d_in, const int* in_sizes, int n_in,
                              void* d_out, int out_size) {
    (void)in_sizes; (void)n_in; (void)out_size;
    const float* x      = (const float*)d_in[0];
    const float* z      = (const float*)d_in[1];
    const float* t      = (const float*)d_in[2];
    const float* freq   = (const float*)d_in[3];
    const float* W1     = (const float*)d_in[4];
    const float* b1     = (const float*)d_in[5];
    const float* W2     = (const float*)d_in[6];
    const float* b2     = (const float*)d_in[7];
    const float* W3     = (const float*)d_in[8];
    const float* b3     = (const float*)d_in[9];
    const float* Wout   = (const float*)d_in[10];
    const float* deltas = (const float*)d_in[11];
    const float* Dbias  = (const float*)d_in[12];
    float* out = (float*)d_out;

    cudaFuncSetAttribute(kf_kernel,   cudaFuncAttributeMaxDynamicSharedMemorySize, SMEM_BYTES);
    cudaFuncSetAttribute(conv_kernel, cudaFuncAttributeMaxDynamicSharedMemorySize, SMEM_BYTES);

    mlp_kernel<<<LSEQ / 4, 256>>>(z, freq, W1, b1, W2, b2, W3, b3);
    filt_kernel<<<dim3(LSEQ / 32, DM / 128), 256>>>(Wout, t, deltas);
    kf_kernel<<<DM, NT, SMEM_BYTES>>>(Dbias);
    conv_kernel<<<dim3(2, DM), NT, SMEM_BYTES>>>(x, out);
}

// round 10
// speedup vs baseline: 1.3607x; 1.0072x over previous
#include <cuda_runtime.h>
#include <math.h>

// Problem constants
#define LSEQ 8192
#define NFFT 16384          // 2*LSEQ = 32*32*16
#define DM   768
#define EMB  33
#define FO   64
#define SHIFT_C 0.05f
#define NT   512            // FFT threads per CTA

// Pad 1 float2 per 16: PHYS(i) = i + (i>>4).  (verified conflict-free R5)
#define DPAD 17408
#define SMEM_BYTES (DPAD * (int)sizeof(float2))          // 139264 B

// ---------------- scratch (device globals: no allocations allowed) ----------
__device__ float g_S[LSEQ * FO];                         // post-MLP activations
__device__ float g_k[DM * LSEQ];                         // filter k[d][l]
__device__ __align__(16) float2 g_Kf[(size_t)DM * NFFT]; // (spectrum + D)/N, scrambled

// cos / (-sin) of 2*pi*k/32 as compile-time constants -> immediate-form FFMA
__device__ static constexpr float CS32[32] = {
    1.0f,                   0.98078528040323044f,  0.92387953251128674f,  0.83146961230254524f,
    0.70710678118654752f,   0.55557023301960222f,  0.38268343236508977f,  0.19509032201612827f,
    0.0f,                  -0.19509032201612827f, -0.38268343236508977f, -0.55557023301960222f,
   -0.70710678118654752f,  -0.83146961230254524f, -0.92387953251128674f, -0.98078528040323044f,
   -1.0f,                  -0.98078528040323044f, -0.92387953251128674f, -0.83146961230254524f,
   -0.70710678118654752f,  -0.55557023301960222f, -0.38268343236508977f, -0.19509032201612827f,
    0.0f,                   0.19509032201612827f,  0.38268343236508977f,  0.55557023301960222f,
    0.70710678118654752f,   0.83146961230254524f,  0.92387953251128674f,  0.98078528040323044f
};
__device__ static constexpr float SN32[32] = {     // = sin(-2*pi*k/32)
    0.0f,                  -0.19509032201612827f, -0.38268343236508977f, -0.55557023301960222f,
   -0.70710678118654752f,  -0.83146961230254524f, -0.92387953251128674f, -0.98078528040323044f,
   -1.0f,                  -0.98078528040323044f, -0.92387953251128674f, -0.83146961230254524f,
   -0.70710678118654752f,  -0.55557023301960222f, -0.38268343236508977f, -0.19509032201612827f,
    0.0f,                   0.19509032201612827f,  0.38268343236508977f,  0.55557023301960222f,
    0.70710678118654752f,   0.83146961230254524f,  0.92387953251128674f,  0.98078528040323044f,
    1.0f,                   0.98078528040323044f,  0.92387953251128674f,  0.83146961230254524f,
    0.70710678118654752f,   0.55557023301960222f,  0.38268343236508977f,  0.19509032201612827f
};

// ---------------- complex helpers ----------------
__device__ __forceinline__ float2 cadd(float2 a, float2 b){ return make_float2(a.x+b.x, a.y+b.y); }
__device__ __forceinline__ float2 csub(float2 a, float2 b){ return make_float2(a.x-b.x, a.y-b.y); }
__device__ __forceinline__ float2 cmul(float2 a, float2 b){
    return make_float2(a.x*b.x - a.y*b.y, a.x*b.y + a.y*b.x);
}
// multiply by compile-time literal (wx, wy): 2 FMUL-imm + 2 FFMA-imm (rt=1)
__device__ __forceinline__ float2 cmuli(float2 a, float wx, float wy) {
    return make_float2(fmaf(a.y, -wy, a.x * wx), fmaf(a.y, wx, a.x * wy));
}
// a * e^{-2*pi*i*k/32}; k folded to constant under #pragma unroll
__device__ __forceinline__ float2 twf(float2 a, int k) {
    k &= 31;
    if (k == 0)  return a;
    if (k == 8)  return make_float2(a.y, -a.x);     // * -i
    if (k == 16) return make_float2(-a.x, -a.y);    // * -1
    if (k == 24) return make_float2(-a.y, a.x);     // * +i
    return cmuli(a, CS32[k], SN32[k]);
}
// a * e^{+2*pi*i*k/32}
__device__ __forceinline__ float2 twb(float2 a, int k) {
    k &= 31;
    if (k == 0)  return a;
    if (k == 8)  return make_float2(-a.y, a.x);     // * +i
    if (k == 16) return make_float2(-a.x, -a.y);    // * -1
    if (k == 24) return make_float2(a.y, -a.x);     // * -i
    return cmuli(a, CS32[k], -SN32[k]);
}

// radix-4 DIF forward core (no twiddle)
__device__ __forceinline__ void bf4f(float2 x0, float2 x1, float2 x2, float2 x3,
                                     float2& a0, float2& a1, float2& a2, float2& a3) {
    float2 t0 = cadd(x0, x2), t1 = csub(x0, x2);
    float2 t2 = cadd(x1, x3), t3 = csub(x1, x3);
    float2 mi = make_float2(t3.y, -t3.x);                // -i * t3
    a0 = cadd(t0, t2);
    a1 = cadd(t1, mi);
    a2 = csub(t0, t2);
    a3 = csub(t1, mi);
}
// radix-4 inverse core (unscaled)
__device__ __forceinline__ void bf4i(float2 x0, float2 x1, float2 x2, float2 x3,
                                     float2& a0, float2& a1, float2& a2, float2& a3) {
    float2 t0 = cadd(x0, x2), t1 = csub(x0, x2);
    float2 t2 = cadd(x1, x3), t3 = csub(x1, x3);
    float2 pi = make_float2(-t3.y, t3.x);                // +i * t3
    a0 = cadd(t0, t2);
    a1 = cadd(t1, pi);
    a2 = csub(t0, t2);
    a3 = csub(t1, pi);
}

// ---------------- register radix-32 (4*4*2 DIF), external span S = 1<<LS ----
// Twiddles: w_m = b^m * e^{-2*pi*i*m*c/32}; b powers hoisted, rotations literal.
// HALF: x[16..31] implicitly zero on entry.
template<int LS, bool HALF>
__device__ __forceinline__ void fft32_fwd(float2* x, int j) {
    const float C = -6.2831853071795864769f / (float)(1 << (LS + 5));
    float sb, cb;
    __sincosf(C * (float)j, &sb, &cb);
    const float2 b  = make_float2(cb, sb);
    const float2 b2 = cmul(b, b);
    const float2 b3 = cmul(b2, b);
    // stage A: span 8
    #pragma unroll
    for (int c = 0; c < 8; c++) {
        float2 w1 = twf(b,  c);
        float2 w2 = twf(b2, 2 * c);
        float2 w3 = twf(b3, 3 * c);
        float2 a0, a1, a2, a3;
        if (HALF) {
            float2 x0 = x[c], x1 = x[c + 8];
            a0 = cadd(x0, x1);
            a1 = make_float2(x0.x + x1.y, x0.y - x1.x);  // x0 - i*x1
            a2 = csub(x0, x1);
            a3 = make_float2(x0.x - x1.y, x0.y + x1.x);  // x0 + i*x1
        } else {
            bf4f(x[c], x[c+8], x[c+16], x[c+24], a0, a1, a2, a3);
        }
        x[c]      = a0;
        x[c + 8]  = cmul(a1, w1);
        x[c + 16] = cmul(a2, w2);
        x[c + 24] = cmul(a3, w3);
    }
    const float2 b4  = cmul(b2, b2);
    const float2 b8  = cmul(b4, b4);
    const float2 b12 = cmul(b8, b4);
    const float2 b16 = cmul(b8, b8);
    // stage B: span 2; twiddles b4^m * e^{-2*pi*i*4*m*c2/32}
    float2 W1[2], W2[2], W3[2];
    W1[0] = b4;  W2[0] = b8;  W3[0] = b12;
    W1[1] = twf(b4, 4);  W2[1] = twf(b8, 8);  W3[1] = twf(b12, 12);
    #pragma unroll
    for (int g = 0; g < 4; g++) {
        #pragma unroll
        for (int c2 = 0; c2 < 2; c2++) {
            const int i = 8 * g + c2;
            float2 a0, a1, a2, a3;
            bf4f(x[i], x[i+2], x[i+4], x[i+6], a0, a1, a2, a3);
            x[i]     = a0;
            x[i + 2] = cmul(a1, W1[c2]);
            x[i + 4] = cmul(a2, W2[c2]);
            x[i + 6] = cmul(a3, W3[c2]);
        }
    }
    // stage C: radix-2, span 1
    #pragma unroll
    for (int m = 0; m < 16; m++) {
        float2 x0 = x[2*m], x1 = x[2*m + 1];
        x[2*m]     = cadd(x0, x1);
        x[2*m + 1] = cmul(csub(x0, x1), b16);
    }
}

// Inverse (unscaled, gain 32).  HALFOUT: only outputs r<16 are produced.
template<int LS, bool HALFOUT>
__device__ __forceinline__ void fft32_inv(float2* x, int j) {
    const float C = -6.2831853071795864769f / (float)(1 << (LS + 5));
    float sb, cb;
    __sincosf(C * (float)j, &sb, &cb);
    const float2 b   = make_float2(cb, -sb);             // conj base
    const float2 b2  = cmul(b, b);
    const float2 b3  = cmul(b2, b);
    const float2 b4  = cmul(b2, b2);
    const float2 b8  = cmul(b4, b4);
    const float2 b12 = cmul(b8, b4);
    const float2 b16 = cmul(b8, b8);
    // stage C'
    #pragma unroll
    for (int m = 0; m < 16; m++) {
        float2 z1 = cmul(x[2*m + 1], b16);
        float2 x0 = x[2*m];
        x[2*m]     = cadd(x0, z1);
        x[2*m + 1] = csub(x0, z1);
    }
    // stage B'
    float2 W1[2], W2[2], W3[2];
    W1[0] = b4;  W2[0] = b8;  W3[0] = b12;
    W1[1] = twb(b4, 4);  W2[1] = twb(b8, 8);  W3[1] = twb(b12, 12);
    #pragma unroll
    for (int g = 0; g < 4; g++) {
        #pragma unroll
        for (int c2 = 0; c2 < 2; c2++) {
            const int i = 8 * g + c2;
            float2 z0 = x[i];
            float2 z1 = cmul(x[i + 2], W1[c2]);
            float2 z2 = cmul(x[i + 4], W2[c2]);
            float2 z3 = cmul(x[i + 6], W3[c2]);
            bf4i(z0, z1, z2, z3, x[i], x[i+2], x[i+4], x[i+6]);
        }
    }
    // stage A'
    #pragma unroll
    for (int c = 0; c < 8; c++) {
        float2 w1 = twb(b,  c);
        float2 w2 = twb(b2, 2 * c);
        float2 w3 = twb(b3, 3 * c);
        float2 z0 = x[c];
        float2 z1 = cmul(x[c + 8],  w1);
        float2 z2 = cmul(x[c + 16], w2);
        float2 z3 = cmul(x[c + 24], w3);
        if (HALFOUT) {
            float2 t0 = cadd(z0, z2), t1 = csub(z0, z2);
            float2 t2 = cadd(z1, z3), t3 = csub(z1, z3);
            float2 pi = make_float2(-t3.y, t3.x);
            x[c]     = cadd(t0, t2);
            x[c + 8] = cadd(t1, pi);
        } else {
            bf4i(z0, z1, z2, z3, x[c], x[c+8], x[c+16], x[c+24]);
        }
    }
}

// ---------------- 16-point cores: ALL twiddles literal ----------------------
// w_m for column c: e^{-2*pi*i*m*c/16} = twf(., 2*m*c)
__device__ __forceinline__ void fft16c_fwd(float2* x) {
    #pragma unroll
    for (int c = 0; c < 4; c++) {
        float2 a0, a1, a2, a3;
        bf4f(x[c], x[c+4], x[c+8], x[c+12], a0, a1, a2, a3);
        x[c]      = a0;
        x[c + 4]  = twf(a1, 2 * c);
        x[c + 8]  = twf(a2, 4 * c);
        x[c + 12] = twf(a3, 6 * c);
    }
    #pragma unroll
    for (int m = 0; m < 4; m++) {
        float2 a0, a1, a2, a3;
        bf4f(x[4*m], x[4*m+1], x[4*m+2], x[4*m+3], a0, a1, a2, a3);
        x[4*m] = a0; x[4*m+1] = a1; x[4*m+2] = a2; x[4*m+3] = a3;
    }
}
__device__ __forceinline__ void fft16c_inv(float2* x) {
    #pragma unroll
    for (int m = 0; m < 4; m++) {
        float2 a0, a1, a2, a3;
        bf4i(x[4*m], x[4*m+1], x[4*m+2], x[4*m+3], a0, a1, a2, a3);
        x[4*m] = a0; x[4*m+1] = a1; x[4*m+2] = a2; x[4*m+3] = a3;
    }
    #pragma unroll
    for (int c = 0; c < 4; c++) {
        float2 z1 = twb(x[c + 4],  2 * c);
        float2 z2 = twb(x[c + 8],  4 * c);
        float2 z3 = twb(x[c + 12], 6 * c);
        bf4i(x[c], z1, z2, z3, x[c], x[c+4], x[c+8], x[c+12]);
    }
}

// ---------------- filter MLP stages 1-3 --------------------------------------
__global__ void mlp_kernel(const float* __restrict__ z, const float* __restrict__ freq,
                           const float* __restrict__ W1, const float* __restrict__ b1,
                           const float* __restrict__ W2, const float* __restrict__ b2,
                           const float* __restrict__ W3, const float* __restrict__ b3) {
    __shared__ float zs[4][EMB];
    __shared__ float as[4][FO];
    __shared__ float bs[4][FO];
    const int tid = threadIdx.x;
    const int lg  = tid >> 6;
    const int f   = tid & 63;
    const int l   = blockIdx.x * 4 + lg;

    if (f < EMB) zs[lg][f] = z[l * EMB + f];
    __syncthreads();

    const float fr = freq[f];

    float acc = b1[f];
    #pragma unroll
    for (int e = 0; e < EMB; e++) acc += zs[lg][e] * W1[e * FO + f];
    as[lg][f] = sinf(fr * acc);
    __syncthreads();

    acc = b2[f];
    #pragma unroll
    for (int e = 0; e < FO; e++) acc += as[lg][e] * W2[e * FO + f];
    bs[lg][f] = sinf(fr * acc);
    __syncthreads();

    acc = b3[f];
    #pragma unroll
    for (int e = 0; e < FO; e++) acc += bs[lg][e] * W3[e * FO + f];
    g_S[l * FO + f] = sinf(fr * acc);
}

// ---------------- output projection + exponential modulation ----------------
__global__ void filt_kernel(const float* __restrict__ Wout, const float* __restrict__ t,
                            const float* __restrict__ deltas) {
    __shared__ float Ss[32][FO];
    __shared__ float Ws[FO][128];
    const int tid = threadIdx.x;
    const int l0  = blockIdx.x * 32;
    const int d0  = blockIdx.y * 128;

    for (int i = tid; i < 32 * FO; i += 256)
        Ss[i >> 6][i & 63] = g_S[(l0 + (i >> 6)) * FO + (i & 63)];
    for (int i = tid; i < FO * 128; i += 256)
        Ws[i >> 7][i & 127] = Wout[(i >> 7) * DM + d0 + (i & 127)];
    __syncthreads();

    const int dl  = tid & 127;
    const int lgp = tid >> 7;
    float acc[16];
    #pragma unroll
    for (int i = 0; i < 16; i++) acc[i] = 0.0f;
    #pragma unroll
    for (int f = 0; f < FO; f++) {
        const float w = Ws[f][dl];
        #pragma unroll
        for (int i = 0; i < 16; i++) acc[i] += Ss[lgp * 16 + i][f] * w;
    }
    const int d = d0 + dl;
    const float ad = fabsf(deltas[d]);
    #pragma unroll
    for (int i = 0; i < 16; i++) {
        const int l = l0 + lgp * 16 + i;
        g_k[(size_t)d * LSEQ + l] = acc[i] * (expf(-t[l] * ad) + SHIFT_C);
    }
}

// ---------------- kernel spectrum (+D baked in) -----------------------------
__global__ void __launch_bounds__(NT, 1)
kf_kernel(const float* __restrict__ Dbias) {
    extern __shared__ float2 d[];
    const int tid = threadIdx.x;
    const int ch  = blockIdx.x;

    const float* krow = g_k + (size_t)ch * LSEQ;
    const int jb = tid + (tid >> 4);                     // PHYS(tid)

    // P1: radix-32, S=512; top half zero
    {
        float2 xv[32];
        #pragma unroll
        for (int r = 0; r < 16; r++)
            xv[r] = make_float2(krow[tid + (r << 9)], 0.0f);
        fft32_fwd<9, true>(xv, tid);
        #pragma unroll
        for (int r = 0; r < 32; r++) d[jb + 544 * r] = xv[r];
    }
    __syncthreads();

    const int j2 = tid & 15;
    const int b0 = (tid >> 4) * 544 + j2;

    // P2: radix-32, S=16
    {
        float2 xv[32];
        #pragma unroll
        for (int r = 0; r < 32; r++) xv[r] = d[b0 + 17 * r];
        fft32_fwd<4, false>(xv, j2);
        #pragma unroll
        for (int r = 0; r < 32; r++) d[b0 + 17 * r] = xv[r];
    }
    __syncthreads();

    // P3: const-twiddle fwd16 + bake (spec + D)/N, store to g_Kf
    float2* outp = g_Kf + (size_t)ch * NFFT;
    const float sc = 1.0f / (float)NFFT;
    const float Dd = Dbias[ch];
    #pragma unroll
    for (int k = 0; k < 2; k++) {
        const int q  = tid + k * NT;
        const int pb = 17 * q;                           // PHYS(16q)
        float2 xv[16];
        #pragma unroll
        for (int r = 0; r < 16; r++) xv[r] = d[pb + r];
        fft16c_fwd(xv);
        float4* o4 = reinterpret_cast<float4*>(outp + 16 * q);
        #pragma unroll
        for (int i = 0; i < 8; i++) {
            o4[i] = make_float4((xv[2*i].x + Dd) * sc, xv[2*i].y * sc,
                                (xv[2*i+1].x + Dd) * sc, xv[2*i+1].y * sc);
        }
    }
}

// ---------------- conv ------------------------------------------------------
// grid = dim3(2, DM): the two batch-pair CTAs of a channel are adjacent in
// linear block order -> co-resident -> second Kf read hits L2.
__global__ void __launch_bounds__(NT, 1)
conv_kernel(const float* __restrict__ x, float* __restrict__ out) {
    extern __shared__ float2 d[];
    const int tid = threadIdx.x;
    const int ch  = blockIdx.y;
    const int p   = blockIdx.x;                          // batch pair

    const float* u0 = x + ((size_t)(2*p)     * DM + ch) * LSEQ;
    const float* u1 = x + ((size_t)(2*p + 1) * DM + ch) * LSEQ;
    const float2* kf = g_Kf + (size_t)ch * NFFT;

    // prefetch this thread's Kf lines into L2 (consumed in P3, ~2500 cyc away)
    asm volatile("prefetch.global.L2 [%0];" :: "l"(kf + 16 * tid));
    asm volatile("prefetch.global.L2 [%0];" :: "l"(kf + 16 * (tid + NT)));

    const int jb = tid + (tid >> 4);

    // P1 fwd: radix-32, S=512; pack u0 + i*u1; top half zero
    {
        float2 xv[32];
        #pragma unroll
        for (int r = 0; r < 16; r++) {
            const int i = tid + (r << 9);
            xv[r] = make_float2(u0[i], u1[i]);
        }
        fft32_fwd<9, true>(xv, tid);
        #pragma unroll
        for (int r = 0; r < 32; r++) d[jb + 544 * r] = xv[r];
    }
    __syncthreads();

    const int j2 = tid & 15;
    const int b0 = (tid >> 4) * 544 + j2;

    // P2 fwd: radix-32, S=16
    {
        float2 xv[32];
        #pragma unroll
        for (int r = 0; r < 32; r++) xv[r] = d[b0 + 17 * r];
        fft32_fwd<4, false>(xv, j2);
        #pragma unroll
        for (int r = 0; r < 32; r++) d[b0 + 17 * r] = xv[r];
    }
    __syncthreads();

    // P3: const-twiddle fwd16 -> * Kf (D baked in) -> const-twiddle inv16
    #pragma unroll
    for (int k = 0; k < 2; k++) {
        const int q  = tid + k * NT;
        const int pb = 17 * q;
        float4 kreg[8];
        const float4* kf4 = reinterpret_cast<const float4*>(kf + 16 * q);
        #pragma unroll
        for (int i = 0; i < 8; i++) kreg[i] = kf4[i];    // prefetch over fwd16
        float2 xv[16];
        #pragma unroll
        for (int r = 0; r < 16; r++) xv[r] = d[pb + r];
        fft16c_fwd(xv);
        #pragma unroll
        for (int i = 0; i < 8; i++) {
            xv[2*i]   = cmul(xv[2*i],   make_float2(kreg[i].x, kreg[i].y));
            xv[2*i+1] = cmul(xv[2*i+1], make_float2(kreg[i].z, kreg[i].w));
        }
        fft16c_inv(xv);
        #pragma unroll
        for (int r = 0; r < 16; r++) d[pb + r] = xv[r];
    }
    __syncthreads();

    // P2' inv
    {
        float2 xv[32];
        #pragma unroll
        for (int r = 0; r < 32; r++) xv[r] = d[b0 + 17 * r];
        fft32_inv<4, false>(xv, j2);
        #pragma unroll
        for (int r = 0; r < 32; r++) d[b0 + 17 * r] = xv[r];
    }
    __syncthreads();

    // P1' inv: half output, direct global store
    float* o0 = out + ((size_t)(2*p)     * DM + ch) * LSEQ;
    float* o1 = out + ((size_t)(2*p + 1) * DM + ch) * LSEQ;
    {
        float2 xv[32];
        #pragma unroll
        for (int r = 0; r < 32; r++) xv[r] = d[jb + 544 * r];
        fft32_inv<9, true>(xv, tid);
        #pragma unroll
        for (int r = 0; r < 16; r++) {
            const int i = tid + (r << 9);
            o0[i] = xv[r].x;
            o1[i] = xv[r].y;
        }
    }
}

// ---------------- launch ----------------------------------------------------
// Input order (metadata): x, z, t, freq, W1, b1, W2, b2, W3, b3, Wout, deltas, D
extern "C" void kernel_launch(void* const* d_in, const int* in_sizes, int n_in,
                              void* d_out, int out_size) {
    (void)in_sizes; (void)n_in; (void)out_size;
    const float* x      = (const float*)d_in[0];
    const float* z      = (const float*)d_in[1];
    const float* t      = (const float*)d_in[2];
    const float* freq   = (const float*)d_in[3];
    const float* W1     = (const float*)d_in[4];
    const float* b1     = (const float*)d_in[5];
    const float* W2     = (const float*)d_in[6];
    const float* b2     = (const float*)d_in[7];
    const float* W3     = (const float*)d_in[8];
    const float* b3     = (const float*)d_in[9];
    const float* Wout   = (const float*)d_in[10];
    const float* deltas = (const float*)d_in[11];
    const float* Dbias  = (const float*)d_in[12];
    float* out = (float*)d_out;

    cudaFuncSetAttribute(kf_kernel,   cudaFuncAttributeMaxDynamicSharedMemorySize, SMEM_BYTES);
    cudaFuncSetAttribute(conv_kernel, cudaFuncAttributeMaxDynamicSharedMemorySize, SMEM_BYTES);

    mlp_kernel<<<LSEQ / 4, 256>>>(z, freq, W1, b1, W2, b2, W3, b3);
    filt_kernel<<<dim3(LSEQ / 32, DM / 128), 256>>>(Wout, t, deltas);
    kf_kernel<<<DM, NT, SMEM_BYTES>>>(Dbias);
    conv_kernel<<<dim3(2, DM), NT, SMEM_BYTES>>>(x, out);
}